// round 17
// baseline (speedup 1.0000x reference)
#include <cuda_runtime.h>
#include <cstddef>

// Problem dims
#define T_STEPS 16
#define B_DIM   64
#define S_DIM   512
#define H_DIM   2048
#define A_DIM   32
#define MROWS   (T_STEPS * B_DIM)          // 1024 (tb rows)
#define NELEM   ((size_t)MROWS * H_DIM)    // 2,097,152
#define MBIG    (T_STEPS * MROWS)          // 16384
#define KWORDS  (H_DIM / 32)               // 64 bit-words per S1 row
#define PSTRIDE ((size_t)MBIG * H_DIM)     // one slice-partial plane
#define ENTCAP  528                        // per-(tb,slice) entries (u64)
#define NSTR    260                        // 256 + 4 pad floats per k-row
#define ZROW    (128u * NSTR * 4u)         // byte offset of the zero pad row

// Output layout: concat of (value, action, m1, m2, m_act, m_crit), fp32
#define OFF_VALUE  0
#define OFF_ACTION 1024
#define OFF_M1     33792
#define OFF_M2     2130944
#define OFF_MACT   4228096
#define OFF_MCRIT  4260864

// Scratch (device globals: allocation-free per harness rules)
__device__ float    g_cur1[MROWS * H_DIM];                  // 8 MB
__device__ float    g_W2T[(size_t)H_DIM * H_DIM];           // 16 MB: W2T[k][n]
__device__ unsigned g_S1bits[(size_t)MBIG * KWORDS];        // 4 MB spike bits
__device__ unsigned long long g_ent[(size_t)MROWS * 4 * ENTCAP]; // 17 MB
__device__ unsigned g_cnt[MROWS * 4];                       // 4x8bit chunk counts
__device__ float    g_P[(size_t)4 * MBIG * H_DIM];          // 512 MB slice partials
__device__ float    g_S2[MROWS * H_DIM];                    // 8 MB

// ---------------------------------------------------------------------------
// Packed f32x2 helpers
// ---------------------------------------------------------------------------
__device__ __forceinline__ unsigned long long pack2(float x, float y) {
    unsigned long long r;
    asm("mov.b64 %0, {%1, %2};" : "=l"(r) : "f"(x), "f"(y));
    return r;
}
__device__ __forceinline__ void fma2(unsigned long long& acc,
                                     unsigned long long a,
                                     unsigned long long b) {
    asm("fma.rn.f32x2 %0, %1, %2, %0;" : "+l"(acc) : "l"(a), "l"(b));
}
__device__ __forceinline__ float2 unpack2(unsigned long long v) {
    float2 f;
    asm("mov.b64 {%0, %1}, %2;" : "=f"(f.x), "=f"(f.y) : "l"(v));
    return f;
}
// ONE bit test (immediate mask) guards FOUR packed adds (256 n per warp).
// Skip / +0.0-pad adds are bit-neutral (acc never -0) — proven rounds 8-16.
template <int BIT>
__device__ __forceinline__ void bitadd4_imm(unsigned long long& r0,
                                            unsigned long long& r1,
                                            unsigned long long& r2,
                                            unsigned long long& r3,
                                            unsigned mask,
                                            unsigned long long w0,
                                            unsigned long long w1,
                                            unsigned long long w2,
                                            unsigned long long w3) {
    asm("{\n\t"
        ".reg .pred p;\n\t"
        ".reg .b32 t;\n\t"
        "and.b32 t, %4, %5;\n\t"
        "setp.ne.b32 p, t, 0;\n\t"
        "@p add.rn.f32x2 %0, %0, %6;\n\t"
        "@p add.rn.f32x2 %1, %1, %7;\n\t"
        "@p add.rn.f32x2 %2, %2, %8;\n\t"
        "@p add.rn.f32x2 %3, %3, %9;\n\t"
        "}"
        : "+l"(r0), "+l"(r1), "+l"(r2), "+l"(r3)
        : "r"(mask), "n"(1 << BIT),
          "l"(w0), "l"(w1), "l"(w2), "l"(w3));
}

#define BITADD8(M, W0, W1, W2, W3)                                             \
    do {                                                                       \
        bitadd4_imm<0>(acc[0][0], acc[0][1], acc[0][2], acc[0][3], (M), W0, W1, W2, W3); \
        bitadd4_imm<1>(acc[1][0], acc[1][1], acc[1][2], acc[1][3], (M), W0, W1, W2, W3); \
        bitadd4_imm<2>(acc[2][0], acc[2][1], acc[2][2], acc[2][3], (M), W0, W1, W2, W3); \
        bitadd4_imm<3>(acc[3][0], acc[3][1], acc[3][2], acc[3][3], (M), W0, W1, W2, W3); \
        bitadd4_imm<4>(acc[4][0], acc[4][1], acc[4][2], acc[4][3], (M), W0, W1, W2, W3); \
        bitadd4_imm<5>(acc[5][0], acc[5][1], acc[5][2], acc[5][3], (M), W0, W1, W2, W3); \
        bitadd4_imm<6>(acc[6][0], acc[6][1], acc[6][2], acc[6][3], (M), W0, W1, W2, W3); \
        bitadd4_imm<7>(acc[7][0], acc[7][1], acc[7][2], acc[7][3], (M), W0, W1, W2, W3); \
    } while (0)

// ---------------------------------------------------------------------------
// W2 transpose: W2T[k][n] = W2[n][k]. 32x32 tiles, once per launch (~5 us).
// ---------------------------------------------------------------------------
__global__ __launch_bounds__(256) void k_transpose(
    const float* __restrict__ W2, float* __restrict__ W2T)
{
    __shared__ float t[32][33];
    const int bk = blockIdx.x * 32;
    const int bn = blockIdx.y * 32;
#pragma unroll
    for (int j = threadIdx.y; j < 32; j += 8)
        t[j][threadIdx.x] = W2[(size_t)(bn + j) * H_DIM + bk + threadIdx.x];
    __syncthreads();
#pragma unroll
    for (int j = threadIdx.y; j < 32; j += 8)
        W2T[(size_t)(bk + j) * H_DIM + bn + threadIdx.x] = t[threadIdx.x][j];
}

// ---------------------------------------------------------------------------
// NT SGEMM for cur1 — BIT-EXACT chain (m1=0 proven rounds 3-16). Unchanged.
// ---------------------------------------------------------------------------
__global__ __launch_bounds__(256) void sgemm_nt(
    const float* __restrict__ A, const float* __restrict__ B,
    const float* __restrict__ bias, float* __restrict__ C,
    int M, int N, int K)
{
    __shared__ float As[8][128];
    __shared__ float Bs[8][128];

    const int tid = threadIdx.x;
    const int bm = blockIdx.y * 128;
    const int bn = blockIdx.x * 128;

    const int lrow = tid >> 1;
    const int lcol = (tid & 1) * 4;

    const int tx = tid & 15;
    const int ty = tid >> 4;

    unsigned long long acc[8][4];
#pragma unroll
    for (int i = 0; i < 8; i++)
#pragma unroll
        for (int j = 0; j < 4; j++) acc[i][j] = 0ULL;

    const float* Aptr = A + (size_t)(bm + lrow) * K + lcol;
    const float* Bptr = B + (size_t)(bn + lrow) * K + lcol;

    for (int k0 = 0; k0 < K; k0 += 8) {
        float4 a4 = *(const float4*)(Aptr + k0);
        float4 b4 = *(const float4*)(Bptr + k0);
        As[lcol + 0][lrow] = a4.x; As[lcol + 1][lrow] = a4.y;
        As[lcol + 2][lrow] = a4.z; As[lcol + 3][lrow] = a4.w;
        Bs[lcol + 0][lrow] = b4.x; Bs[lcol + 1][lrow] = b4.y;
        Bs[lcol + 2][lrow] = b4.z; Bs[lcol + 3][lrow] = b4.w;
        __syncthreads();

#pragma unroll
        for (int k = 0; k < 8; k++) {
            float ar[8];
            float4 t;
            t = *(const float4*)&As[k][ty * 8];     ar[0]=t.x; ar[1]=t.y; ar[2]=t.z; ar[3]=t.w;
            t = *(const float4*)&As[k][ty * 8 + 4]; ar[4]=t.x; ar[5]=t.y; ar[6]=t.z; ar[7]=t.w;
            float4 b0 = *(const float4*)&Bs[k][tx * 8];
            float4 b1 = *(const float4*)&Bs[k][tx * 8 + 4];
            unsigned long long bp[4];
            bp[0] = pack2(b0.x, b0.y); bp[1] = pack2(b0.z, b0.w);
            bp[2] = pack2(b1.x, b1.y); bp[3] = pack2(b1.z, b1.w);
#pragma unroll
            for (int i = 0; i < 8; i++) {
                unsigned long long ap = pack2(ar[i], ar[i]);
#pragma unroll
                for (int j = 0; j < 4; j++)
                    fma2(acc[i][j], ap, bp[j]);
            }
        }
        __syncthreads();
    }

    const int row0 = bm + ty * 8;
    const int col0 = bn + tx * 8;
#pragma unroll
    for (int i = 0; i < 8; i++) {
#pragma unroll
        for (int jv = 0; jv < 2; jv++) {
            float2 p0 = unpack2(acc[i][jv * 2 + 0]);
            float2 p1 = unpack2(acc[i][jv * 2 + 1]);
            float4 v;
            v.x = __fadd_rn(p0.x, bias[col0 + jv * 4 + 0]);
            v.y = __fadd_rn(p0.y, bias[col0 + jv * 4 + 1]);
            v.z = __fadd_rn(p1.x, bias[col0 + jv * 4 + 2]);
            v.w = __fadd_rn(p1.y, bias[col0 + jv * 4 + 3]);
            *(float4*)(C + (size_t)(row0 + i) * N + col0 + jv * 4) = v;
        }
    }
}

// ---------------------------------------------------------------------------
// m1 scan (BIT-EXACT chain) — emits spike bits via ballot. Unchanged.
// ---------------------------------------------------------------------------
__global__ void k_scan1(const float* __restrict__ cur1,
                        const float* __restrict__ mem1,
                        const float* __restrict__ beta1p,
                        float* __restrict__ m1_out,
                        unsigned* __restrict__ S1bits)
{
    size_t e = (size_t)blockIdx.x * blockDim.x + threadIdx.x;
    if (e >= NELEM) return;
    const int lane = threadIdx.x & 31;
    const size_t row = e / H_DIM;
    const size_t wcol = (e % H_DIM) >> 5;
    const float beta = *beta1p;
    const float c = cur1[e];
    float m = mem1[e];
#pragma unroll
    for (int k = 0; k < T_STEPS; k++) {
        float reset = (m > 1.0f) ? 1.0f : 0.0f;
        m = __fsub_rn(fmaf(beta, m, c), reset);
        unsigned w = __ballot_sync(0xFFFFFFFFu, m > 1.0f);
        if (lane == 0)
            S1bits[((size_t)k * MROWS + row) * KWORDS + wcol] = w;
    }
    m1_out[e] = m;
}

// ---------------------------------------------------------------------------
// Index prepass v4: per (tb, slice) union lists split into FOUR 128-k chunks
// (ascending k, chunk-relative byte offsets (k&127)*NSTR*4, 16-bit step
// masks in hi32). Each chunk padded to even count with {ZROW,0}; +8 trailing
// pads. cnt = t0p | t1p<<8 | t2p<<16 | t3p<<24.
// One warp per (tb, slice); lane l<16 owns k-word l (4 lanes per chunk).
// ---------------------------------------------------------------------------
__global__ __launch_bounds__(256) void k_index(
    const unsigned* __restrict__ S1bits,
    unsigned long long* __restrict__ ent, unsigned* __restrict__ cnt)
{
    const int task = (blockIdx.x * blockDim.x + threadIdx.x) >> 5;
    const int lane = threadIdx.x & 31;
    if (task >= MROWS * 4) return;
    const int tb = task >> 2;
    const int s  = task & 3;

    unsigned w16[T_STEPS];
    unsigned uni = 0;
#pragma unroll
    for (int st = 0; st < T_STEPS; st++) {
        unsigned w = 0;
        if (lane < 16)
            w = S1bits[((size_t)st * MROWS + tb) * KWORDS + s * 16 + lane];
        w16[st] = w;
        uni |= w;
    }
    int c = __popc(uni);

    int incl = c;
#pragma unroll
    for (int o = 1; o < 32; o <<= 1) {
        int v = __shfl_up_sync(0xFFFFFFFFu, incl, o);
        if (lane >= o) incl += v;
    }
    int excl = incl - c;
    int e3  = __shfl_sync(0xFFFFFFFFu, incl, 3);
    int e7  = __shfl_sync(0xFFFFFFFFu, incl, 7);
    int e11 = __shfl_sync(0xFFFFFFFFu, incl, 11);
    int e15 = __shfl_sync(0xFFFFFFFFu, incl, 15);
    int t0 = e3, t1 = e7 - e3, t2 = e11 - e7, t3 = e15 - e11;
    int t0p = (t0 + 1) & ~1, t1p = (t1 + 1) & ~1;
    int t2p = (t2 + 1) & ~1, t3p = (t3 + 1) & ~1;
    int b1 = t0p, b2 = t0p + t1p, b3 = t0p + t1p + t2p;

    const int chunk = (lane >> 2) & 3;
    int cbase, cstart;
    if (chunk == 0)      { cbase = 0;  cstart = 0; }
    else if (chunk == 1) { cbase = b1; cstart = e3; }
    else if (chunk == 2) { cbase = b2; cstart = e7; }
    else                 { cbase = b3; cstart = e11; }

    unsigned long long* base = ent + (size_t)task * ENTCAP;
    int pos = cbase + (excl - cstart);
    unsigned u = uni;
    while (u) {
        int b = __ffs(u) - 1;
        u &= u - 1;
        unsigned mask = 0;
#pragma unroll
        for (int st = 0; st < T_STEPS; st++)
            mask |= ((w16[st] >> b) & 1u) << st;
        unsigned off = (unsigned)((lane & 3) * 32 + b) * (NSTR * 4);
        base[pos++] = ((unsigned long long)mask << 32) | off;
    }
    if (lane == 0) {
        if (t0 & 1) base[t0]      = (unsigned long long)ZROW;
        if (t1 & 1) base[b1 + t1] = (unsigned long long)ZROW;
        if (t2 & 1) base[b2 + t2] = (unsigned long long)ZROW;
        if (t3 & 1) base[b3 + t3] = (unsigned long long)ZROW;
        int end = b3 + t3p;
        int pend = end + 8;
        if (pend > ENTCAP) pend = ENTCAP;
        for (int p = end; p < pend; p++)
            base[p] = (unsigned long long)ZROW;
        cnt[task] = (unsigned)(t0p | (t1p << 8) | (t2p << 16) | (t3p << 24));
    }
}

// ---------------------------------------------------------------------------
// SPARSE big GEMM v9: 256 n per warp, 16 steps split across a warp PAIR
// (warp = (tb-row, half); half h owns steps 8h..8h+7, tests bits of
// mask>>8h). ONE bit test guards FOUR packed adds. Slice = four 128-k tile
// chunks, accs persisting across reloads -> ascending-k per slice = PROVEN
// sliced1x4 chain per step. Skips/pads bit-neutral.
// Grid (8 nblk, 128 tb-groups, 4 slices), 512 threads, ~134 KB smem.
// ---------------------------------------------------------------------------
__global__ __launch_bounds__(512) void sgemm_sparse(
    const float* __restrict__ W2T,
    const unsigned long long* __restrict__ ent, const unsigned* __restrict__ cnt,
    float* __restrict__ P)
{
    extern __shared__ float sm[];        // [129][NSTR]
    const int tid  = threadIdx.x;
    const int lane = tid & 31;
    const int warp = tid >> 5;
    const int half = warp & 1;
    const int hs   = half * 8;
    const int n0 = blockIdx.x * 256;
    const int tb = blockIdx.y * 8 + (warp >> 1);
    const int s  = blockIdx.z;

    const int task = tb * 4 + s;
    const unsigned cw = cnt[task];
    const unsigned long long* list = ent + (size_t)task * ENTCAP;

    unsigned long long acc[8][4];
#pragma unroll
    for (int st = 0; st < 8; st++)
#pragma unroll
        for (int j = 0; j < 4; j++) acc[st][j] = 0ULL;

    const char* smL = (const char*)sm + 32 * lane;   // lane's 8-n column (32B)
    int lbase = 0;

#pragma unroll 1
    for (int chunk = 0; chunk < 4; chunk++) {
        __syncthreads();
        // Tile: sm[k*NSTR + n] = W2T[s*512 + chunk*128 + k][n0 + n]
        {
            const float* Wb = W2T + (size_t)(s * 512 + chunk * 128) * H_DIM + n0;
            for (int i = tid; i < 128 * 64; i += 512) {
                int k = i >> 6;
                int q = (i & 63) * 4;
                *(float4*)(sm + k * NSTR + q) =
                    *(const float4*)(Wb + (size_t)k * H_DIM + q);
            }
            if (tid < NSTR) sm[128 * NSTR + tid] = 0.0f;   // zero pad row
        }
        __syncthreads();

        const int tp = (int)((cw >> (8 * chunk)) & 0xFFu);
        const int nv = tp >> 1;
        const uint4* lp = (const uint4*)(list + lbase);
        lbase += tp;

        uint4 q0 = lp[0], q1 = lp[1];
        ulonglong2 a0 = *(const ulonglong2*)(smL + q0.x);
        ulonglong2 a1 = *(const ulonglong2*)(smL + q0.x + 16);
        ulonglong2 c0 = *(const ulonglong2*)(smL + q0.z);
        ulonglong2 c1 = *(const ulonglong2*)(smL + q0.z + 16);

#pragma unroll 2
        for (int j = 0; j < nv; j++) {
            uint4 qn = lp[j + 2];
            ulonglong2 na0 = *(const ulonglong2*)(smL + q1.x);
            ulonglong2 na1 = *(const ulonglong2*)(smL + q1.x + 16);
            ulonglong2 nc0 = *(const ulonglong2*)(smL + q1.z);
            ulonglong2 nc1 = *(const ulonglong2*)(smL + q1.z + 16);
            const unsigned hm0 = q0.y >> hs;
            const unsigned hm1 = q0.w >> hs;
            BITADD8(hm0, a0.x, a0.y, a1.x, a1.y);
            BITADD8(hm1, c0.x, c0.y, c1.x, c1.y);
            q0 = q1; q1 = qn;
            a0 = na0; a1 = na1; c0 = nc0; c1 = nc1;
        }
    }

    float* Pb = P + (size_t)s * PSTRIDE + n0 + 8 * lane;
#pragma unroll
    for (int st = 0; st < 8; st++) {
        float* row = Pb + ((size_t)(st + hs) * MROWS + tb) * H_DIM;
        ulonglong2 v0, v1;
        v0.x = acc[st][0]; v0.y = acc[st][1];
        v1.x = acc[st][2]; v1.y = acc[st][3];
        *(ulonglong2*)row = v0;
        *(ulonglong2*)(row + 4) = v1;
    }
}

// ---------------------------------------------------------------------------
// m2 scan with fused slice merge: h = (((P0+P1)+P2)+P3) + b2, then the
// proven FMA-form leaky chain. Unchanged (measured correct rounds 9-16).
// ---------------------------------------------------------------------------
__global__ void k_scan2(const float* __restrict__ P,
                        const float* __restrict__ b2,
                        const float* __restrict__ mem2,
                        const float* __restrict__ beta2p,
                        float* __restrict__ m2_out,
                        float* __restrict__ S2)
{
    size_t e = (size_t)blockIdx.x * blockDim.x + threadIdx.x;
    if (e >= NELEM) return;
    const float beta = *beta2p;
    const float bias = b2[e & (H_DIM - 1)];
    float m = mem2[e];
#pragma unroll
    for (int k = 0; k < T_STEPS; k++) {
        size_t o = (size_t)k * NELEM + e;
        float h = __fadd_rn(P[o], P[PSTRIDE + o]);
        h = __fadd_rn(h, P[2 * PSTRIDE + o]);
        h = __fadd_rn(h, P[3 * PSTRIDE + o]);
        h = __fadd_rn(h, bias);
        float reset = (m > 1.0f) ? 1.0f : 0.0f;
        m = __fsub_rn(fmaf(beta, m, h), reset);
    }
    m2_out[e] = m;
    S2[e] = (m > 1.0f) ? 1.0f : 0.0f;
}

// ---------------------------------------------------------------------------
// Heads: value/action + leaky epilogues (FMA form). One block per row.
// ---------------------------------------------------------------------------
__global__ __launch_bounds__(256) void k_heads(
    const float* __restrict__ S2,
    const float* __restrict__ Wc, const float* __restrict__ bc,
    const float* __restrict__ Wa, const float* __restrict__ ba,
    const float* __restrict__ mem_act, const float* __restrict__ mem_crit,
    const float* __restrict__ beta_critp, const float* __restrict__ beta_actp,
    float* __restrict__ out)
{
    const int i = blockIdx.x;
    __shared__ float row[H_DIM];
    for (int h = threadIdx.x; h < H_DIM; h += blockDim.x)
        row[h] = S2[(size_t)i * H_DIM + h];
    __syncthreads();

    float acc[33];
#pragma unroll
    for (int a = 0; a < 33; a++) acc[a] = 0.0f;

    for (int h = threadIdx.x; h < H_DIM; h += blockDim.x) {
        float s = row[h];
        if (s != 0.0f) {
            acc[0] += Wc[h];
#pragma unroll
            for (int a = 0; a < 32; a++)
                acc[a + 1] += Wa[(size_t)a * H_DIM + h];
        }
    }

#pragma unroll
    for (int a = 0; a < 33; a++)
#pragma unroll
        for (int off = 16; off > 0; off >>= 1)
            acc[a] += __shfl_xor_sync(0xFFFFFFFFu, acc[a], off);

    __shared__ float part[8][33];
    const int wid = threadIdx.x >> 5, lane = threadIdx.x & 31;
    if (lane == 0) {
#pragma unroll
        for (int a = 0; a < 33; a++) part[wid][a] = acc[a];
    }
    __syncthreads();

    if (threadIdx.x < 33) {
        const int a = threadIdx.x;
        float y = 0.0f;
#pragma unroll
        for (int w = 0; w < 8; w++) y += part[w][a];
        if (a == 0) {
            y = __fadd_rn(y, bc[0]);
            const float beta = *beta_critp;
            float mem = mem_crit[i];
            float reset = (mem > 1.0f) ? 1.0f : 0.0f;
            float m = __fsub_rn(fmaf(beta, mem, y), reset);
            out[OFF_VALUE + i] = (m > 1.0f) ? 1.0f : 0.0f;
            out[OFF_MCRIT + i] = m;
        } else {
            const int j = a - 1;
            y = __fadd_rn(y, ba[j]);
            const float beta = *beta_actp;
            float mem = mem_act[(size_t)i * A_DIM + j];
            float reset = (mem > 1.0f) ? 1.0f : 0.0f;
            float m = __fsub_rn(fmaf(beta, mem, y), reset);
            out[OFF_ACTION + (size_t)i * A_DIM + j] = (m > 1.0f) ? 1.0f : 0.0f;
            out[OFF_MACT + (size_t)i * A_DIM + j] = m;
        }
    }
}

// ---------------------------------------------------------------------------
extern "C" void kernel_launch(void* const* d_in, const int* in_sizes, int n_in,
                              void* d_out, int out_size)
{
    const float* inputs   = (const float*)d_in[0];
    const float* mem1     = (const float*)d_in[1];
    const float* mem2     = (const float*)d_in[2];
    const float* mem_act  = (const float*)d_in[3];
    const float* mem_crit = (const float*)d_in[4];
    const float* W1 = (const float*)d_in[5];
    const float* b1 = (const float*)d_in[6];
    const float* W2 = (const float*)d_in[7];
    const float* b2 = (const float*)d_in[8];
    const float* Wc = (const float*)d_in[9];
    const float* bc = (const float*)d_in[10];
    const float* Wa = (const float*)d_in[11];
    const float* ba = (const float*)d_in[12];
    const float* beta1     = (const float*)d_in[13];
    const float* beta2     = (const float*)d_in[14];
    const float* beta_crit = (const float*)d_in[15];
    const float* beta_act  = (const float*)d_in[16];
    float* out = (float*)d_out;

    float *cur1, *W2T, *Pp, *S2;
    unsigned *S1bits, *cnt;
    unsigned long long* ent;
    cudaGetSymbolAddress((void**)&cur1, g_cur1);
    cudaGetSymbolAddress((void**)&W2T, g_W2T);
    cudaGetSymbolAddress((void**)&S1bits, g_S1bits);
    cudaGetSymbolAddress((void**)&ent, g_ent);
    cudaGetSymbolAddress((void**)&cnt, g_cnt);
    cudaGetSymbolAddress((void**)&Pp, g_P);
    cudaGetSymbolAddress((void**)&S2, g_S2);

    static const int SMEM_BYTES = 129 * NSTR * 4;  // 134160
    cudaFuncSetAttribute(sgemm_sparse,
                         cudaFuncAttributeMaxDynamicSharedMemorySize,
                         SMEM_BYTES);

    // 0) W2 transpose (once per launch)
    k_transpose<<<dim3(H_DIM / 32, H_DIM / 32), dim3(32, 8)>>>(W2, W2T);

    // 1) cur1 = inputs @ W1^T + b1 (bit-exact chain)
    sgemm_nt<<<dim3(H_DIM / 128, MROWS / 128), 256>>>(
        inputs, W1, b1, cur1, MROWS, H_DIM, S_DIM);

    // 2) m1 scan -> spike bits + m1 final
    k_scan1<<<(unsigned)((NELEM + 255) / 256), 256>>>(
        cur1, mem1, beta1, out + OFF_M1, S1bits);

    // 3) index prepass v4: 4-chunk union lists with step masks
    k_index<<<(MROWS * 4) / 8, 256>>>(S1bits, ent, cnt);

    // 4) sparse big GEMM v9: 256n per warp, step-halved warp pairs
    sgemm_sparse<<<dim3(H_DIM / 256, MROWS / 8, 4), 512, SMEM_BYTES>>>(
        W2T, ent, cnt, Pp);

    // 5) m2 scan with fused slice merge + bias -> m2 final, S2 spikes
    k_scan2<<<(unsigned)((NELEM + 255) / 256), 256>>>(
        Pp, b2, mem2, beta2, out + OFF_M2, S2);

    // 6) heads
    k_heads<<<MROWS, 256>>>(S2, Wc, bc, Wa, ba, mem_act, mem_crit,
                            beta_crit, beta_act, out);
}